// round 1
// baseline (speedup 1.0000x reference)
#include <cuda_runtime.h>
#include <math.h>

// GCN: 4 layers, N=100000 nodes, E=3200000 edges (+ implicit self loops).
// Layers 1 and 4 reduced to SCALAR edge aggregations (linear-algebra identity);
// only layers 2,3 need 32-wide aggregation. Self-loops folded into epilogues.

#define MAXN 100000
#define MAXE 3200000

__device__ float g_dinv[MAXN];       // degree -> rsqrt(degree)
__device__ float g_s[MAXN];          // scalar aggregation accumulator
__device__ float g_t[MAXN];          // scalar transformed feature (layer 4)
__device__ float g_norm[MAXE];       // per-edge norm = dinv[src]*dinv[dst]
__device__ float g_H[MAXN * 32];     // current features
__device__ float g_Ht[MAXN * 32];    // transformed features
__device__ float g_Hn[MAXN * 32];    // aggregation accumulator (32-wide)

__global__ void k_init_nodes(int n) {
    int i = blockIdx.x * blockDim.x + threadIdx.x;
    if (i < n) { g_dinv[i] = 1.0f; g_s[i] = 0.0f; }   // deg starts at 1 (self loop)
}

__global__ void k_init_Hn(int n32) {
    int i = blockIdx.x * blockDim.x + threadIdx.x;
    if (i < n32) g_Hn[i] = 0.0f;
}

__global__ void k_deg(const int* __restrict__ dst, int e) {
    int i = blockIdx.x * blockDim.x + threadIdx.x;
    if (i < e) atomicAdd(&g_dinv[dst[i]], 1.0f);
}

__global__ void k_dinv(int n) {
    int i = blockIdx.x * blockDim.x + threadIdx.x;
    if (i < n) g_dinv[i] = rsqrtf(g_dinv[i]);
}

// Fused: compute per-edge norm AND do the layer-1 scalar aggregation.
__global__ void k_norm_l1(const int* __restrict__ src, const int* __restrict__ dst,
                          const float* __restrict__ x, int e) {
    int i = blockIdx.x * blockDim.x + threadIdx.x;
    if (i >= e) return;
    int a = __ldg(src + i);
    int b = __ldg(dst + i);
    float nr = __ldg(&g_dinv[a]) * __ldg(&g_dinv[b]);
    g_norm[i] = nr;
    atomicAdd(&g_s[b], __ldg(x + a) * nr);
}

// H1[i][c] = relu((s[i] + dinv[i]^2 * x[i]) * W_in[c] + b_in[c])
__global__ void k_l1_expand(const float* __restrict__ x, const float* __restrict__ Win,
                            const float* __restrict__ bin, int n) {
    int idx = blockIdx.x * blockDim.x + threadIdx.x;
    if (idx >= n * 32) return;
    int i = idx >> 5, c = idx & 31;
    float di = g_dinv[i];
    float tot = g_s[i] + di * di * __ldg(x + i);
    g_H[idx] = fmaxf(fmaf(tot, __ldg(Win + c), __ldg(bin + c)), 0.0f);
}

// Ht = H @ W (32x32). One warp per node; W staged in shared memory.
__global__ void k_transform(const float* __restrict__ W, int n) {
    __shared__ float sW[1024];
    for (int k = threadIdx.x; k < 1024; k += blockDim.x) sW[k] = W[k];
    __syncthreads();
    int idx = blockIdx.x * blockDim.x + threadIdx.x;
    int i = idx >> 5, lane = idx & 31;
    if (i >= n) return;
    float hv = g_H[idx];
    float acc = 0.0f;
#pragma unroll
    for (int k = 0; k < 32; k++) {
        float hk = __shfl_sync(0xffffffffu, hv, k);
        acc = fmaf(hk, sW[k * 32 + lane], acc);
    }
    g_Ht[idx] = acc;
}

// 32-wide edge scatter: one warp per edge. Hn[dst][c] += Ht[src][c] * norm.
__global__ void k_scatter(const int* __restrict__ src, const int* __restrict__ dst, int e) {
    int gt = blockIdx.x * blockDim.x + threadIdx.x;
    int w = gt >> 5, lane = gt & 31;
    if (w >= e) return;
    int a = __ldg(src + w);
    int b = __ldg(dst + w);
    float nr = __ldg(&g_norm[w]);
    atomicAdd(&g_Hn[b * 32 + lane], g_Ht[a * 32 + lane] * nr);
}

// H[i][c] = relu(Hn[i][c] + dinv[i]^2 * Ht[i][c] + b[c]); re-zero Hn for next layer.
__global__ void k_epilogue(const float* __restrict__ bmid, int n) {
    int idx = blockIdx.x * blockDim.x + threadIdx.x;
    if (idx >= n * 32) return;
    int i = idx >> 5, c = idx & 31;
    float di = g_dinv[i];
    float v = g_Hn[idx] + di * di * g_Ht[idx] + __ldg(bmid + c);
    g_H[idx] = fmaxf(v, 0.0f);
    g_Hn[idx] = 0.0f;
}

// t[i] = H[i] . W_out  (warp reduction); also zero g_s for layer-4 aggregation.
__global__ void k_out_transform(const float* __restrict__ Wout, int n) {
    int idx = blockIdx.x * blockDim.x + threadIdx.x;
    int i = idx >> 5, lane = idx & 31;
    if (i >= n) return;
    float v = g_H[idx] * __ldg(Wout + lane);
#pragma unroll
    for (int o = 16; o; o >>= 1) v += __shfl_xor_sync(0xffffffffu, v, o);
    if (lane == 0) g_t[i] = v;
    if (lane == 1) g_s[i] = 0.0f;
}

__global__ void k_out_agg(const int* __restrict__ src, const int* __restrict__ dst, int e) {
    int i = blockIdx.x * blockDim.x + threadIdx.x;
    if (i >= e) return;
    int a = __ldg(src + i);
    int b = __ldg(dst + i);
    atomicAdd(&g_s[b], __ldg(&g_t[a]) * g_norm[i]);
}

__global__ void k_out_final(const float* __restrict__ bout, float* __restrict__ out, int n) {
    int i = blockIdx.x * blockDim.x + threadIdx.x;
    if (i >= n) return;
    float di = g_dinv[i];
    float v = g_s[i] + di * di * g_t[i] + __ldg(bout);
    out[i] = 1.0f / (1.0f + expf(-v));
}

extern "C" void kernel_launch(void* const* d_in, const int* in_sizes, int n_in,
                              void* d_out, int out_size) {
    const float* x    = (const float*)d_in[0];
    const int*   ei   = (const int*)  d_in[1];
    const float* Win  = (const float*)d_in[2];
    const float* bin  = (const float*)d_in[3];
    const float* Wmid = (const float*)d_in[4];
    const float* bmid = (const float*)d_in[5];
    const float* Wout = (const float*)d_in[6];
    const float* bout = (const float*)d_in[7];

    int n = in_sizes[0];
    int e = in_sizes[1] / 2;
    const int* src = ei;
    const int* dst = ei + e;

    const int B = 256;
    int gN   = (n + B - 1) / B;
    int gN32 = (n * 32 + B - 1) / B;
    int gE   = (e + B - 1) / B;
    long long e32 = (long long)e * 32;
    int gE32 = (int)((e32 + B - 1) / B);

    // degrees / norms / layer-1 scalar aggregation
    k_init_nodes<<<gN, B>>>(n);
    k_init_Hn<<<gN32, B>>>(n * 32);
    k_deg<<<gE, B>>>(dst, e);
    k_dinv<<<gN, B>>>(n);
    k_norm_l1<<<gE, B>>>(src, dst, x, e);
    k_l1_expand<<<gN32, B>>>(x, Win, bin, n);

    // layer 2 (wide)
    k_transform<<<gN32, B>>>(Wmid, n);
    k_scatter<<<gE32, B>>>(src, dst, e);
    k_epilogue<<<gN32, B>>>(bmid, n);

    // layer 3 (wide)
    k_transform<<<gN32, B>>>(Wmid, n);
    k_scatter<<<gE32, B>>>(src, dst, e);
    k_epilogue<<<gN32, B>>>(bmid, n);

    // layer 4 (scalar)
    k_out_transform<<<gN32, B>>>(Wout, n);
    k_out_agg<<<gE, B>>>(src, dst, e);
    k_out_final<<<gN, B>>>(bout, (float*)d_out, n);
}

// round 2
// speedup vs baseline: 2.3373x; 2.3373x over previous
#include <cuda_runtime.h>
#include <math.h>

// GCN 4-layer, pull-based. Per-call CSR build (hist + 2-level scan + fill),
// then every aggregation is an atomic-free gather fused with its epilogue.
// norm = dinv[s]*dinv[d] factored into features: Hts = dinv*(H@W), result =
// dinv[i]*(sum_in Hts[src] + Hts[i]) + b.   (self-loop folded analytically)

#define MAXN 100000
#define MAXE 3200000
#define SCAN_B 256
#define MAX_BLKS 512   // ceil(100000/256)=391 < 512

__device__ int   g_cnt[MAXN];          // in-degree (excl. self loop)
__device__ int   g_rowpart[MAXN];      // block-local exclusive scan
__device__ int   g_bsum[MAX_BLKS];     // per-block sums -> exclusive scanned
__device__ int   g_rowstart[MAXN];     // CSR row starts
__device__ int   g_cursor[MAXN];       // fill cursors
__device__ int   g_adj[MAXE];          // CSR: src ids grouped by dst
__device__ float g_dinv[MAXN];
__device__ float g_xs[MAXN];           // dinv[i]*x[i]
__device__ float g_t[MAXN];            // scaled scalar feature (layer 4)
__device__ float g_H[MAXN * 32];       // activations
__device__ float g_Ht[MAXN * 32];      // Hts = dinv * (H @ W)

__global__ void k_zero_cnt(int n) {
    int i = blockIdx.x * blockDim.x + threadIdx.x;
    if (i < n) g_cnt[i] = 0;
}

__global__ void k_hist(const int* __restrict__ dst, int e) {
    int i = blockIdx.x * blockDim.x + threadIdx.x;
    if (i < e) atomicAdd(&g_cnt[__ldg(dst + i)], 1);
}

__global__ void k_scan1(int n) {
    __shared__ int sh[SCAN_B];
    int tid = threadIdx.x;
    int i = blockIdx.x * SCAN_B + tid;
    int v = (i < n) ? g_cnt[i] : 0;
    sh[tid] = v;
    __syncthreads();
#pragma unroll
    for (int o = 1; o < SCAN_B; o <<= 1) {
        int t = (tid >= o) ? sh[tid - o] : 0;
        __syncthreads();
        sh[tid] += t;
        __syncthreads();
    }
    if (i < n) g_rowpart[i] = sh[tid] - v;          // exclusive
    if (tid == SCAN_B - 1) g_bsum[blockIdx.x] = sh[tid];
}

__global__ void k_scan2(int nb) {
    __shared__ int sh[MAX_BLKS];
    int tid = threadIdx.x;
    int v = (tid < nb) ? g_bsum[tid] : 0;
    sh[tid] = v;
    __syncthreads();
#pragma unroll
    for (int o = 1; o < MAX_BLKS; o <<= 1) {
        int t = (tid >= o) ? sh[tid - o] : 0;
        __syncthreads();
        sh[tid] += t;
        __syncthreads();
    }
    if (tid < nb) g_bsum[tid] = sh[tid] - v;        // exclusive
}

// rowstart/cursor + dinv + xs, fused.
__global__ void k_scan3(const float* __restrict__ x, int n) {
    int i = blockIdx.x * blockDim.x + threadIdx.x;
    if (i >= n) return;
    int rs = g_rowpart[i] + g_bsum[blockIdx.x * blockDim.x / SCAN_B + (threadIdx.x / SCAN_B)];
    g_rowstart[i] = rs;
    g_cursor[i] = rs;
    float di = rsqrtf((float)g_cnt[i] + 1.0f);      // +1 = self loop
    g_dinv[i] = di;
    g_xs[i] = di * __ldg(x + i);
}

__global__ void k_fill(const int* __restrict__ src, const int* __restrict__ dst, int e) {
    int i = blockIdx.x * blockDim.x + threadIdx.x;
    if (i >= e) return;
    int pos = atomicAdd(&g_cursor[__ldg(dst + i)], 1);
    g_adj[pos] = __ldg(src + i);
}

// Layer 1 fused: scalar pull + expand to 32 channels. Warp per node.
__global__ void k_l1(const float* __restrict__ Win, const float* __restrict__ bin, int n) {
    int gt = blockIdx.x * blockDim.x + threadIdx.x;
    int i = gt >> 5, lane = gt & 31;
    if (i >= n) return;
    int rs = g_rowstart[i];
    int deg = g_cnt[i];
    float s = 0.0f;
    for (int j = lane; j < deg; j += 32)
        s += __ldg(&g_xs[__ldg(&g_adj[rs + j])]);
#pragma unroll
    for (int o = 16; o; o >>= 1) s += __shfl_xor_sync(0xffffffffu, s, o);
    float di = g_dinv[i];
    float tot = di * (s + g_xs[i]);
    g_H[i * 32 + lane] = fmaxf(fmaf(tot, __ldg(Win + lane), __ldg(bin + lane)), 0.0f);
}

// Hts = dinv[i] * (H @ W). Warp per node, W staged in shared.
__global__ void k_transform(const float* __restrict__ W, int n) {
    __shared__ float sW[1024];
    for (int k = threadIdx.x; k < 1024; k += blockDim.x) sW[k] = W[k];
    __syncthreads();
    int gt = blockIdx.x * blockDim.x + threadIdx.x;
    int i = gt >> 5, lane = gt & 31;
    if (i >= n) return;
    float hv = g_H[gt];
    float acc = 0.0f;
#pragma unroll
    for (int k = 0; k < 32; k++) {
        float hk = __shfl_sync(0xffffffffu, hv, k);
        acc = fmaf(hk, sW[k * 32 + lane], acc);
    }
    g_Ht[gt] = g_dinv[i] * acc;
}

// Wide pull fused with epilogue. Warp per node; lane = channel.
__global__ void k_pull(const float* __restrict__ b, int n) {
    int gt = blockIdx.x * blockDim.x + threadIdx.x;
    int i = gt >> 5, lane = gt & 31;
    if (i >= n) return;
    int rs = g_rowstart[i];
    int deg = g_cnt[i];
    float acc = 0.0f;
    for (int base = 0; base < deg; base += 32) {
        int rem = deg - base;
        int lim = rem < 32 ? rem : 32;
        int eidx = (lane < lim) ? __ldg(&g_adj[rs + base + lane]) : 0;
        for (int k = 0; k < lim; k++) {
            int s = __shfl_sync(0xffffffffu, eidx, k);
            acc += __ldg(&g_Ht[s * 32 + lane]);
        }
    }
    float v = g_dinv[i] * (acc + g_Ht[gt]) + __ldg(b + lane);
    g_H[gt] = fmaxf(v, 0.0f);
}

// ts = dinv[i] * (H[i] . Wout). Warp per node.
__global__ void k_out_transform(const float* __restrict__ Wout, int n) {
    int gt = blockIdx.x * blockDim.x + threadIdx.x;
    int i = gt >> 5, lane = gt & 31;
    if (i >= n) return;
    float v = g_H[gt] * __ldg(Wout + lane);
#pragma unroll
    for (int o = 16; o; o >>= 1) v += __shfl_xor_sync(0xffffffffu, v, o);
    if (lane == 0) g_t[i] = g_dinv[i] * v;
}

// Final scalar pull + sigmoid. Warp per node.
__global__ void k_out(const float* __restrict__ bout, float* __restrict__ out, int n) {
    int gt = blockIdx.x * blockDim.x + threadIdx.x;
    int i = gt >> 5, lane = gt & 31;
    if (i >= n) return;
    int rs = g_rowstart[i];
    int deg = g_cnt[i];
    float s = 0.0f;
    for (int j = lane; j < deg; j += 32)
        s += __ldg(&g_t[__ldg(&g_adj[rs + j])]);
#pragma unroll
    for (int o = 16; o; o >>= 1) s += __shfl_xor_sync(0xffffffffu, s, o);
    if (lane == 0) {
        float v = g_dinv[i] * (s + g_t[i]) + __ldg(bout);
        out[i] = 1.0f / (1.0f + expf(-v));
    }
}

extern "C" void kernel_launch(void* const* d_in, const int* in_sizes, int n_in,
                              void* d_out, int out_size) {
    const float* x    = (const float*)d_in[0];
    const int*   ei   = (const int*)  d_in[1];
    const float* Win  = (const float*)d_in[2];
    const float* bin  = (const float*)d_in[3];
    const float* Wmid = (const float*)d_in[4];
    const float* bmid = (const float*)d_in[5];
    const float* Wout = (const float*)d_in[6];
    const float* bout = (const float*)d_in[7];

    int n = in_sizes[0];
    int e = in_sizes[1] / 2;
    const int* src = ei;
    const int* dst = ei + e;

    const int B = 256;
    int gN   = (n + B - 1) / B;                 // also the scan block count
    int gN32 = (n * 32 + B - 1) / B;
    int gE   = (e + B - 1) / B;

    // CSR build
    k_zero_cnt<<<gN, B>>>(n);
    k_hist<<<gE, B>>>(dst, e);
    k_scan1<<<gN, SCAN_B>>>(n);
    k_scan2<<<1, MAX_BLKS>>>(gN);
    k_scan3<<<gN, B>>>(x, n);
    k_fill<<<gE, B>>>(src, dst, e);

    // layer 1 (scalar pull -> expand)
    k_l1<<<gN32, B>>>(Win, bin, n);

    // layers 2,3 (wide pull)
    k_transform<<<gN32, B>>>(Wmid, n);
    k_pull<<<gN32, B>>>(bmid, n);
    k_transform<<<gN32, B>>>(Wmid, n);
    k_pull<<<gN32, B>>>(bmid, n);

    // layer 4 (scalar pull -> sigmoid)
    k_out_transform<<<gN32, B>>>(Wout, n);
    k_out<<<gN32, B>>>(bout, (float*)d_out, n);
}

// round 3
// speedup vs baseline: 2.6131x; 1.1180x over previous
#include <cuda_runtime.h>
#include <math.h>

// GCN 4-layer, pull-based CSR, transforms FUSED into pull epilogues.
// Per-layer: warp pulls neighbor rows of Ht (scaled transformed feats),
// applies relu epilogue -> node activation row lives in warp registers ->
// immediately applies next layer's 32x32 transform via shfl-FMA -> writes
// next Ht. No separate H array, no separate transform kernels.

#define MAXN 100000
#define MAXE 3200000
#define SCAN_B 256
#define MAX_BLKS 512

__device__ int   g_cnt[MAXN];
__device__ int   g_rowpart[MAXN];
__device__ int   g_bsum[MAX_BLKS];
__device__ int   g_rowstart[MAXN];
__device__ int   g_cursor[MAXN];
__device__ int   g_adj[MAXE];
__device__ float g_dinv[MAXN];
__device__ float g_xs[MAXN];           // dinv[i]*x[i]
__device__ float g_t[MAXN];            // scaled scalar feature (layer 4)
__device__ float g_HtA[MAXN * 32];     // ping
__device__ float g_HtB[MAXN * 32];     // pong

__global__ void k_zero_cnt(int n) {
    int i = blockIdx.x * blockDim.x + threadIdx.x;
    if (i < n) g_cnt[i] = 0;
}

__global__ void k_hist(const int* __restrict__ dst, int e) {
    int i = blockIdx.x * blockDim.x + threadIdx.x;
    if (i < e) atomicAdd(&g_cnt[__ldg(dst + i)], 1);
}

__global__ void k_scan1(int n) {
    __shared__ float dummy; (void)dummy;
    __shared__ int sh[SCAN_B];
    int tid = threadIdx.x;
    int i = blockIdx.x * SCAN_B + tid;
    int v = (i < n) ? g_cnt[i] : 0;
    sh[tid] = v;
    __syncthreads();
#pragma unroll
    for (int o = 1; o < SCAN_B; o <<= 1) {
        int t = (tid >= o) ? sh[tid - o] : 0;
        __syncthreads();
        sh[tid] += t;
        __syncthreads();
    }
    if (i < n) g_rowpart[i] = sh[tid] - v;
    if (tid == SCAN_B - 1) g_bsum[blockIdx.x] = sh[tid];
}

// Single-block scan of up to 512 block sums, shfl-based (fast).
__global__ void k_scan2(int nb) {
    __shared__ int wsum[16];
    int tid = threadIdx.x;          // 512 threads
    int lane = tid & 31, w = tid >> 5;
    int v = (tid < nb) ? g_bsum[tid] : 0;
    int s = v;
#pragma unroll
    for (int o = 1; o < 32; o <<= 1) {
        int t = __shfl_up_sync(0xffffffffu, s, o);
        if (lane >= o) s += t;
    }
    if (lane == 31) wsum[w] = s;
    __syncthreads();
    if (w == 0) {
        int ws = (lane < 16) ? wsum[lane] : 0;
#pragma unroll
        for (int o = 1; o < 16; o <<= 1) {
            int t = __shfl_up_sync(0xffffffffu, ws, o);
            if (lane >= o) ws += t;
        }
        if (lane < 16) wsum[lane] = ws;
    }
    __syncthreads();
    int off = (w > 0) ? wsum[w - 1] : 0;
    if (tid < nb) g_bsum[tid] = off + s - v;   // exclusive
}

__global__ void k_scan3(const float* __restrict__ x, int n) {
    int i = blockIdx.x * blockDim.x + threadIdx.x;
    if (i >= n) return;
    int rs = g_rowpart[i] + g_bsum[i / SCAN_B];
    g_rowstart[i] = rs;
    g_cursor[i] = rs;
    float di = rsqrtf((float)g_cnt[i] + 1.0f);
    g_dinv[i] = di;
    g_xs[i] = di * __ldg(x + i);
}

__global__ void k_fill(const int* __restrict__ src, const int* __restrict__ dst, int e) {
    int i = blockIdx.x * blockDim.x + threadIdx.x;
    if (i >= e) return;
    int pos = atomicAdd(&g_cursor[__ldg(dst + i)], 1);
    g_adj[pos] = __ldg(src + i);
}

// Layer 1 fused: scalar pull -> expand -> W_mid transform -> HtA.
__global__ void k_l1(const float* __restrict__ Win, const float* __restrict__ bin,
                     const float* __restrict__ Wmid, int n) {
    __shared__ float sW[1024];
    for (int k = threadIdx.x; k < 1024; k += blockDim.x) sW[k] = Wmid[k];
    __syncthreads();
    int gt = blockIdx.x * blockDim.x + threadIdx.x;
    int i = gt >> 5, lane = gt & 31;
    if (i >= n) return;
    int rs = g_rowstart[i];
    int deg = g_cnt[i];
    float s = 0.0f;
    for (int j = lane; j < deg; j += 32)
        s += __ldg(&g_xs[__ldg(&g_adj[rs + j])]);
#pragma unroll
    for (int o = 16; o; o >>= 1) s += __shfl_xor_sync(0xffffffffu, s, o);
    float di = g_dinv[i];
    float tot = di * (s + g_xs[i]);
    float hv = fmaxf(fmaf(tot, __ldg(Win + lane), __ldg(bin + lane)), 0.0f);
    // fused transform: HtA = dinv * (h1 @ Wmid)
    float acc = 0.0f;
#pragma unroll
    for (int k = 0; k < 32; k++) {
        float hk = __shfl_sync(0xffffffffu, hv, k);
        acc = fmaf(hk, sW[k * 32 + lane], acc);
    }
    g_HtA[gt] = di * acc;
}

// Layer 2 fused: wide pull of HtA -> relu epilogue -> W_mid transform -> HtB.
__global__ void k_pull2(const float* __restrict__ bmid, const float* __restrict__ Wmid, int n) {
    __shared__ float sW[1024];
    for (int k = threadIdx.x; k < 1024; k += blockDim.x) sW[k] = Wmid[k];
    __syncthreads();
    int gt = blockIdx.x * blockDim.x + threadIdx.x;
    int i = gt >> 5, lane = gt & 31;
    if (i >= n) return;
    int rs = g_rowstart[i];
    int deg = g_cnt[i];
    float acc = 0.0f;
    for (int base = 0; base < deg; base += 32) {
        int rem = deg - base;
        int lim = rem < 32 ? rem : 32;
        int eidx = (lane < lim) ? __ldg(&g_adj[rs + base + lane]) : 0;
        for (int k = 0; k < lim; k++) {
            int s = __shfl_sync(0xffffffffu, eidx, k);
            acc += __ldg(&g_HtA[s * 32 + lane]);
        }
    }
    float di = g_dinv[i];
    float hv = fmaxf(di * (acc + g_HtA[gt]) + __ldg(bmid + lane), 0.0f);
    float acc2 = 0.0f;
#pragma unroll
    for (int k = 0; k < 32; k++) {
        float hk = __shfl_sync(0xffffffffu, hv, k);
        acc2 = fmaf(hk, sW[k * 32 + lane], acc2);
    }
    g_HtB[gt] = di * acc2;
}

// Layer 3 fused: wide pull of HtB -> relu -> dot W_out -> scalar t.
__global__ void k_pull3(const float* __restrict__ bmid, const float* __restrict__ Wout, int n) {
    int gt = blockIdx.x * blockDim.x + threadIdx.x;
    int i = gt >> 5, lane = gt & 31;
    if (i >= n) return;
    int rs = g_rowstart[i];
    int deg = g_cnt[i];
    float acc = 0.0f;
    for (int base = 0; base < deg; base += 32) {
        int rem = deg - base;
        int lim = rem < 32 ? rem : 32;
        int eidx = (lane < lim) ? __ldg(&g_adj[rs + base + lane]) : 0;
        for (int k = 0; k < lim; k++) {
            int s = __shfl_sync(0xffffffffu, eidx, k);
            acc += __ldg(&g_HtB[s * 32 + lane]);
        }
    }
    float di = g_dinv[i];
    float hv = fmaxf(di * (acc + g_HtB[gt]) + __ldg(bmid + lane), 0.0f);
    float v = hv * __ldg(Wout + lane);
#pragma unroll
    for (int o = 16; o; o >>= 1) v += __shfl_xor_sync(0xffffffffu, v, o);
    if (lane == 0) g_t[i] = di * v;
}

// Final scalar pull + sigmoid.
__global__ void k_out(const float* __restrict__ bout, float* __restrict__ out, int n) {
    int gt = blockIdx.x * blockDim.x + threadIdx.x;
    int i = gt >> 5, lane = gt & 31;
    if (i >= n) return;
    int rs = g_rowstart[i];
    int deg = g_cnt[i];
    float s = 0.0f;
    for (int j = lane; j < deg; j += 32)
        s += __ldg(&g_t[__ldg(&g_adj[rs + j])]);
#pragma unroll
    for (int o = 16; o; o >>= 1) s += __shfl_xor_sync(0xffffffffu, s, o);
    if (lane == 0) {
        float v = g_dinv[i] * (s + g_t[i]) + __ldg(bout);
        out[i] = 1.0f / (1.0f + expf(-v));
    }
}

extern "C" void kernel_launch(void* const* d_in, const int* in_sizes, int n_in,
                              void* d_out, int out_size) {
    const float* x    = (const float*)d_in[0];
    const int*   ei   = (const int*)  d_in[1];
    const float* Win  = (const float*)d_in[2];
    const float* bin  = (const float*)d_in[3];
    const float* Wmid = (const float*)d_in[4];
    const float* bmid = (const float*)d_in[5];
    const float* Wout = (const float*)d_in[6];
    const float* bout = (const float*)d_in[7];

    int n = in_sizes[0];
    int e = in_sizes[1] / 2;
    const int* src = ei;
    const int* dst = ei + e;

    const int B = 256;
    int gN   = (n + B - 1) / B;
    int gN32 = (n * 32 + B - 1) / B;
    int gE   = (e + B - 1) / B;

    // CSR build
    k_zero_cnt<<<gN, B>>>(n);
    k_hist<<<gE, B>>>(dst, e);
    k_scan1<<<gN, SCAN_B>>>(n);
    k_scan2<<<1, 512>>>(gN);
    k_scan3<<<gN, B>>>(x, n);
    k_fill<<<gE, B>>>(src, dst, e);

    // fused layers
    k_l1<<<gN32, B>>>(Win, bin, Wmid, n);
    k_pull2<<<gN32, B>>>(bmid, Wmid, n);
    k_pull3<<<gN32, B>>>(bmid, Wout, n);
    k_out<<<gN32, B>>>(bout, (float*)d_out, n);
}

// round 4
// speedup vs baseline: 2.9630x; 1.1339x over previous
#include <cuda_runtime.h>
#include <cuda_bf16.h>
#include <math.h>

// GCN 4-layer, pull-based CSR, fused transforms, bf16 feature rows,
// 2-edges-per-iteration wide pull (lanes split into two 16-lane groups,
// each lane accumulates 2 channels as float2; groups combined via shfl_xor).

#define MAXN 100000
#define MAXE 3200000
#define SCAN_B 256
#define MAX_BLKS 512

__device__ int   g_cnt[MAXN];           // zero at entry (zero-init + piggyback re-zero)
__device__ int   g_rowpart[MAXN];
__device__ int   g_bsum[MAX_BLKS];
__device__ int   g_rows[MAXN + 1];      // rowstart, sentinel [n]=e
__device__ int   g_cursor[MAXN];
__device__ int   g_adj[MAXE];
__device__ float g_dinv[MAXN];
__device__ float g_xs[MAXN];            // dinv[i]*x[i]
__device__ float g_t[MAXN];             // scaled scalar feature (layer 4)
__device__ __nv_bfloat162 g_HtA[MAXN * 16];   // 32 bf16 channels per node
__device__ __nv_bfloat162 g_HtB[MAXN * 16];

__global__ void k_hist(const int* __restrict__ dst, int e) {
    int i = blockIdx.x * blockDim.x + threadIdx.x;
    if (i < e) atomicAdd(&g_cnt[__ldg(dst + i)], 1);
}

// 256-thread block scan, shfl-based.
__global__ void k_scan1(int n) {
    __shared__ int wsum[8];
    int tid = threadIdx.x, lane = tid & 31, w = tid >> 5;
    int i = blockIdx.x * SCAN_B + tid;
    int v = (i < n) ? g_cnt[i] : 0;
    int s = v;
#pragma unroll
    for (int o = 1; o < 32; o <<= 1) {
        int t = __shfl_up_sync(0xffffffffu, s, o);
        if (lane >= o) s += t;
    }
    if (lane == 31) wsum[w] = s;
    __syncthreads();
    if (w == 0 && lane < 8) {
        int ws = wsum[lane];
#pragma unroll
        for (int o = 1; o < 8; o <<= 1) {
            int t = __shfl_up_sync(0x000000ffu, ws, o);
            if (lane >= o) ws += t;
        }
        wsum[lane] = ws;
    }
    __syncthreads();
    int off = (w > 0) ? wsum[w - 1] : 0;
    if (i < n) g_rowpart[i] = off + s - v;          // exclusive
    if (tid == SCAN_B - 1) g_bsum[blockIdx.x] = off + s;
}

// Single-block scan of up to 512 block sums.
__global__ void k_scan2(int nb) {
    __shared__ int wsum[16];
    int tid = threadIdx.x, lane = tid & 31, w = tid >> 5;
    int v = (tid < nb) ? g_bsum[tid] : 0;
    int s = v;
#pragma unroll
    for (int o = 1; o < 32; o <<= 1) {
        int t = __shfl_up_sync(0xffffffffu, s, o);
        if (lane >= o) s += t;
    }
    if (lane == 31) wsum[w] = s;
    __syncthreads();
    if (w == 0) {
        int ws = (lane < 16) ? wsum[lane] : 0;
#pragma unroll
        for (int o = 1; o < 16; o <<= 1) {
            int t = __shfl_up_sync(0xffffffffu, ws, o);
            if (lane >= o) ws += t;
        }
        if (lane < 16) wsum[lane] = ws;
    }
    __syncthreads();
    int off = (w > 0) ? wsum[w - 1] : 0;
    if (tid < nb) g_bsum[tid] = off + s - v;        // exclusive
}

__global__ void k_scan3(const float* __restrict__ x, int n, int e) {
    int i = blockIdx.x * blockDim.x + threadIdx.x;
    if (i >= n) return;
    int rs = g_rowpart[i] + g_bsum[i / SCAN_B];
    g_rows[i] = rs;
    g_cursor[i] = rs;
    if (i == 0) g_rows[n] = e;
    float di = rsqrtf((float)g_cnt[i] + 1.0f);      // +1 self loop
    g_dinv[i] = di;
    g_xs[i] = di * __ldg(x + i);
}

__global__ void k_fill(const int* __restrict__ src, const int* __restrict__ dst, int e) {
    int i = blockIdx.x * blockDim.x + threadIdx.x;
    if (i >= e) return;
    int pos = atomicAdd(&g_cursor[__ldg(dst + i)], 1);
    g_adj[pos] = __ldg(src + i);
}

// Layer 1: scalar pull -> expand -> W_mid transform -> HtA (bf16).
__global__ void k_l1(const float* __restrict__ Win, const float* __restrict__ bin,
                     const float* __restrict__ Wmid, int n) {
    __shared__ float sW[1024];
    for (int k = threadIdx.x; k < 1024; k += blockDim.x) sW[k] = Wmid[k];
    __syncthreads();
    int gt = blockIdx.x * blockDim.x + threadIdx.x;
    int i = gt >> 5, lane = gt & 31;
    if (i >= n) return;
    int rs = g_rows[i];
    int deg = g_rows[i + 1] - rs;
    if (lane == 1) g_cnt[i] = 0;                    // re-zero for next replay
    float s = 0.0f;
    for (int j = lane; j < deg; j += 32)
        s += __ldg(&g_xs[__ldg(&g_adj[rs + j])]);
#pragma unroll
    for (int o = 16; o; o >>= 1) s += __shfl_xor_sync(0xffffffffu, s, o);
    float di = g_dinv[i];
    float tot = di * (s + g_xs[i]);
    float hv = fmaxf(fmaf(tot, __ldg(Win + lane), __ldg(bin + lane)), 0.0f);
    float acc = 0.0f;
#pragma unroll
    for (int k = 0; k < 32; k++) {
        float hk = __shfl_sync(0xffffffffu, hv, k);
        acc = fmaf(hk, sW[k * 32 + lane], acc);
    }
    ((__nv_bfloat16*)g_HtA)[i * 32 + lane] = __float2bfloat16(di * acc);
}

// Wide pull core: returns per-lane channel value of dinv*(sum_nbr + self).
// Ht rows are 16 x bf16x2. Two edges per iteration (16-lane groups).
__device__ __forceinline__ float wide_pull(const __nv_bfloat162* __restrict__ Hb,
                                           int i, int lane) {
    int rs = g_rows[i];
    int deg = g_rows[i + 1] - rs;
    int grp = lane >> 4;          // 0/1: which edge of the pair
    int cl  = lane & 15;          // channel-pair index
    float ax = 0.0f, ay = 0.0f;
    for (int base = 0; base < deg; base += 32) {
        int rem = deg - base;
        int lim = rem < 32 ? rem : 32;
        int eidx = (lane < lim) ? __ldg(&g_adj[rs + base + lane]) : 0;
        int half = (lim + 1) >> 1;
        for (int k = 0; k < half; k++) {
            int eoff = 2 * k + grp;
            int sidx = __shfl_sync(0xffffffffu, eidx, eoff);
            if (eoff < lim) {
                float2 f = __bfloat1622float2(__ldg(&Hb[sidx * 16 + cl]));
                ax += f.x; ay += f.y;
            }
        }
    }
    ax += __shfl_xor_sync(0xffffffffu, ax, 16);
    ay += __shfl_xor_sync(0xffffffffu, ay, 16);
    // self term (added identically in both group copies)
    float2 fs = __bfloat1622float2(Hb[i * 16 + cl]);
    ax += fs.x; ay += fs.y;
    // redistribute: channel c=lane lives at lane c>>1, component c&1
    float vx = __shfl_sync(0xffffffffu, ax, lane >> 1);
    float vy = __shfl_sync(0xffffffffu, ay, lane >> 1);
    return (lane & 1) ? vy : vx;
}

// Layer 2: wide pull HtA -> relu -> W_mid transform -> HtB (bf16).
__global__ void k_pull2(const float* __restrict__ bmid, const float* __restrict__ Wmid, int n) {
    __shared__ float sW[1024];
    for (int k = threadIdx.x; k < 1024; k += blockDim.x) sW[k] = Wmid[k];
    __syncthreads();
    int gt = blockIdx.x * blockDim.x + threadIdx.x;
    int i = gt >> 5, lane = gt & 31;
    if (i >= n) return;
    float aggr = wide_pull(g_HtA, i, lane);
    float di = g_dinv[i];
    float hv = fmaxf(fmaf(di, aggr, __ldg(bmid + lane)), 0.0f);
    float acc = 0.0f;
#pragma unroll
    for (int k = 0; k < 32; k++) {
        float hk = __shfl_sync(0xffffffffu, hv, k);
        acc = fmaf(hk, sW[k * 32 + lane], acc);
    }
    ((__nv_bfloat16*)g_HtB)[i * 32 + lane] = __float2bfloat16(di * acc);
}

// Layer 3: wide pull HtB -> relu -> dot W_out -> scalar t.
__global__ void k_pull3(const float* __restrict__ bmid, const float* __restrict__ Wout, int n) {
    int gt = blockIdx.x * blockDim.x + threadIdx.x;
    int i = gt >> 5, lane = gt & 31;
    if (i >= n) return;
    float aggr = wide_pull(g_HtB, i, lane);
    float di = g_dinv[i];
    float hv = fmaxf(fmaf(di, aggr, __ldg(bmid + lane)), 0.0f);
    float v = hv * __ldg(Wout + lane);
#pragma unroll
    for (int o = 16; o; o >>= 1) v += __shfl_xor_sync(0xffffffffu, v, o);
    if (lane == 0) g_t[i] = di * v;
}

// Layer 4: scalar pull + sigmoid.
__global__ void k_out(const float* __restrict__ bout, float* __restrict__ out, int n) {
    int gt = blockIdx.x * blockDim.x + threadIdx.x;
    int i = gt >> 5, lane = gt & 31;
    if (i >= n) return;
    int rs = g_rows[i];
    int deg = g_rows[i + 1] - rs;
    float s = 0.0f;
    for (int j = lane; j < deg; j += 32)
        s += __ldg(&g_t[__ldg(&g_adj[rs + j])]);
#pragma unroll
    for (int o = 16; o; o >>= 1) s += __shfl_xor_sync(0xffffffffu, s, o);
    if (lane == 0) {
        float v = g_dinv[i] * (s + g_t[i]) + __ldg(bout);
        out[i] = 1.0f / (1.0f + expf(-v));
    }
}

extern "C" void kernel_launch(void* const* d_in, const int* in_sizes, int n_in,
                              void* d_out, int out_size) {
    const float* x    = (const float*)d_in[0];
    const int*   ei   = (const int*)  d_in[1];
    const float* Win  = (const float*)d_in[2];
    const float* bin  = (const float*)d_in[3];
    const float* Wmid = (const float*)d_in[4];
    const float* bmid = (const float*)d_in[5];
    const float* Wout = (const float*)d_in[6];
    const float* bout = (const float*)d_in[7];

    int n = in_sizes[0];
    int e = in_sizes[1] / 2;
    const int* src = ei;
    const int* dst = ei + e;

    const int B = 256;
    int gN   = (n + B - 1) / B;
    int gN32 = (n * 32 + B - 1) / B;
    int gE   = (e + B - 1) / B;

    // CSR build (g_cnt is zero at entry: zero-init first call, piggyback after)
    k_hist<<<gE, B>>>(dst, e);
    k_scan1<<<gN, SCAN_B>>>(n);
    k_scan2<<<1, 512>>>(gN);
    k_scan3<<<gN, B>>>(x, n, e);
    k_fill<<<gE, B>>>(src, dst, e);

    // fused layers
    k_l1<<<gN32, B>>>(Win, bin, Wmid, n);
    k_pull2<<<gN32, B>>>(bmid, Wmid, n);
    k_pull3<<<gN32, B>>>(bmid, Wout, n);
    k_out<<<gN32, B>>>(bout, (float*)d_out, n);
}